// round 16
// baseline (speedup 1.0000x reference)
#include <cuda_runtime.h>
#include <cuda_fp16.h>
#include <float.h>
#include <stdint.h>

// ---------------------------------------------------------------------------
#define BB   32
#define CC   256
#define HWD  1024
#define KK   1024
#define NN   (BB * HWD)        // 32768
#define BM   128               // query rows per CTA
#define NCHUNK 32              // 8 nt * 4 kc (single fp16 product)

// SMEM layout for GEMM kernel
#define SM_A        0                   // [128 m][256 k] fp16 swizzled = 65536
#define SM_B        65536               // 4 stages x [128 n][64 k] fp16 = 65536
#define SM_B_BUF    16384
#define SM_SS       131072              // score staging half[128][136] = 34816
#define SS_PITCH    136
#define SMEM_TOTAL  (131072 + 128 * SS_PITCH * 2)   // 165888
#define EPI_SMEM    (CC * BM * 4)                   // 131072

// Certified bound: |true - stored_score| <= xn*0.0035*sqrt(wsq) + 0.5
// (0.2 register-path slack validated in R10 + 0.3 fp16 score-storage rounding)
#define E_CONST 0.5f

// ---------------------------------------------------------------------------
// Device scratch (static globals — no allocation)
__device__ __align__(256) __half g_w1[KK * CC];              // w fp16 [n][k]
__device__ __align__(256) __half g_z1[NN * CC];              // z fp16 [m][k]
__device__ __align__(256) float  g_zt[NN * CC];              // z fp32 [m][c]
__device__ __align__(256) __half g_scores[(size_t)NN * KK];  // approx scores, fp16
__device__ float    g_wsq[KK];
__device__ unsigned g_slmax_bits;        // max over k of 0.0035*sqrt(wsq_k), float bits
__device__ float    g_xnp[8 * NN];       // per-row partial |x|^2 (8 c-blocks)
__device__ int      g_ridx[NN];

// ---------------------------------------------------------------------------
__device__ __forceinline__ uint32_t smem_u32(const void* p) {
    return (uint32_t)__cvta_generic_to_shared(p);
}
__device__ __forceinline__ void cpa16(uint32_t s, const void* g) {
    asm volatile("cp.async.cg.shared.global [%0], [%1], 16;\n" :: "r"(s), "l"(g));
}
#define CPA_COMMIT() asm volatile("cp.async.commit_group;\n" ::: "memory")
#define CPA_WAIT(n)  asm volatile("cp.async.wait_group %0;\n" :: "n"(n) : "memory")

__device__ __forceinline__ void ldsm4(uint32_t* r, uint32_t addr) {
    asm volatile("ldmatrix.sync.aligned.m8n8.x4.shared.b16 {%0,%1,%2,%3}, [%4];"
                 : "=r"(r[0]), "=r"(r[1]), "=r"(r[2]), "=r"(r[3]) : "r"(addr));
}
__device__ __forceinline__ void mma16816(float* d, const uint32_t* a,
                                         uint32_t b0, uint32_t b1) {
    asm volatile("mma.sync.aligned.m16n8k16.row.col.f32.f16.f16.f32 "
                 "{%0,%1,%2,%3}, {%4,%5,%6,%7}, {%8,%9}, {%0,%1,%2,%3};"
                 : "+f"(d[0]), "+f"(d[1]), "+f"(d[2]), "+f"(d[3])
                 : "r"(a[0]), "r"(a[1]), "r"(a[2]), "r"(a[3]), "r"(b0), "r"(b1));
}

// ---------------------------------------------------------------------------
// Prep: w -> fp16 copy + wsq + global max slope. One warp per code.
__global__ void prep_w_kernel(const float* __restrict__ w) {
    int code = blockIdx.x * 8 + (threadIdx.x >> 5);
    int lane = threadIdx.x & 31;
    const float* row = w + (size_t)code * CC;
    float4 v0 = *(const float4*)(row + lane * 8);
    float4 v1 = *(const float4*)(row + lane * 8 + 4);
    float s = v0.x*v0.x + v0.y*v0.y + v0.z*v0.z + v0.w*v0.w
            + v1.x*v1.x + v1.y*v1.y + v1.z*v1.z + v1.w*v1.w;
    __half h[8];
    h[0]=__float2half_rn(v0.x); h[1]=__float2half_rn(v0.y);
    h[2]=__float2half_rn(v0.z); h[3]=__float2half_rn(v0.w);
    h[4]=__float2half_rn(v1.x); h[5]=__float2half_rn(v1.y);
    h[6]=__float2half_rn(v1.z); h[7]=__float2half_rn(v1.w);
    *(uint4*)(g_w1 + (size_t)code * CC + lane * 8) = *(uint4*)h;
    #pragma unroll
    for (int o = 16; o; o >>= 1) s += __shfl_down_sync(0xffffffffu, s, o);
    if (lane == 0) {
        g_wsq[code] = s;
        atomicMax(&g_slmax_bits, __float_as_uint(0.0035f * sqrtf(s)));
    }
}

// Transpose z -> g_z1 fp16 / g_zt fp32, plus per-row 32c-block norm partials.
__global__ void zprep_kernel(const float* __restrict__ z) {
    __shared__ float t[32][33];
    int c0  = blockIdx.x * 32;
    int hw0 = blockIdx.y * 32;
    int b   = blockIdx.z;
    int x = threadIdx.x, y0 = threadIdx.y;     // 32 x 8; warp = fixed y0
    const float* zb = z + ((size_t)b * CC) * HWD;
    #pragma unroll
    for (int yy = 0; yy < 32; yy += 8)
        t[y0 + yy][x] = zb[(size_t)(c0 + y0 + yy) * HWD + hw0 + x];
    __syncthreads();
    #pragma unroll
    for (int yy = 0; yy < 32; yy += 8) {
        int hwl = y0 + yy;
        float v = t[x][hwl];
        size_t o = (size_t)(b * HWD + hw0 + hwl) * CC + c0 + x;
        g_zt[o] = v;
        g_z1[o] = __float2half_rn(v);
        float p = v * v;
        #pragma unroll
        for (int sh = 16; sh; sh >>= 1) p += __shfl_xor_sync(0xffffffffu, p, sh);
        if (x == 0)
            g_xnp[(c0 >> 5) * NN + b * HWD + hw0 + hwl] = p;
    }
}

// ---------------------------------------------------------------------------
__device__ __forceinline__ void load_b_chunk(uint32_t Bbase, int c, int slot, int tid) {
    int nt = c >> 2, kc = c & 3;
    const __half* base = g_w1 + ((size_t)(nt * 128) << 8) + (kc << 6);
    uint32_t dst = Bbase + slot * SM_B_BUF;
    #pragma unroll
    for (int j = 0; j < 2; ++j) {
        int gi = j * 512 + tid;
        int r = gi >> 3, g = gi & 7;
        cpa16(dst + r * 128 + ((g ^ (r & 7)) << 4),
              base + ((size_t)r << 8) + (g << 3));
    }
}

// ---------------------------------------------------------------------------
// Bare 1-product HMMA GEMM; stores fp16 APPROX SCORES (wsq - 2*dot).
__global__ __launch_bounds__(512, 1)
void vq_gemm_kernel() {
    extern __shared__ __align__(1024) char smem[];
    const int tid  = threadIdx.x;
    const int lane = tid & 31;
    const int wid  = tid >> 5;
    const int wm   = wid >> 2;
    const int wn   = wid & 3;

    const int n0 = blockIdx.x * BM;

    const uint32_t sbase = smem_u32(smem);
    const uint32_t Abase = sbase + SM_A;
    const uint32_t Bbase = sbase + SM_B;

    #pragma unroll
    for (int j = 0; j < 8; ++j) {
        int gi = j * 512 + tid;
        int m = gi >> 5, g = gi & 31;
        cpa16(Abase + m * 512 + ((g ^ (m & 7)) << 4),
              g_z1 + ((size_t)(n0 + m) << 8) + (g << 3));
    }
    load_b_chunk(Bbase, 0, 0, tid);
    CPA_COMMIT();
    load_b_chunk(Bbase, 1, 1, tid);
    CPA_COMMIT();
    load_b_chunk(Bbase, 2, 2, tid);
    CPA_COMMIT();

    const uint32_t a_row = wm * 32 + (lane & 15);
    const uint32_t a_ghi = lane >> 4;
    const uint32_t a_rx  = a_row & 7;
    const uint32_t a_addr0 = Abase + a_row * 512;

    uint32_t b_addr0[2], b_gx[2];
    #pragma unroll
    for (int bl = 0; bl < 2; ++bl) {
        uint32_t nr = wn * 32 + bl * 16 + (lane & 15);
        b_addr0[bl] = Bbase + nr * 128;
        b_gx[bl] = nr & 7;
    }

    float acc[2][4][4];

    for (int c = 0; c < NCHUNK; ++c) {
        const int nt   = c >> 2;
        const int kc   = c & 3;
        const int slot = c & 3;

        if (c + 2 < NCHUNK)      CPA_WAIT(2);
        else if (c + 1 < NCHUNK) CPA_WAIT(1);
        else                     CPA_WAIT(0);
        __syncthreads();
        if (c + 3 < NCHUNK) {
            load_b_chunk(Bbase, c + 3, (c + 3) & 3, tid);
            CPA_COMMIT();
        }

        if (kc == 0) {
            #pragma unroll
            for (int i = 0; i < 2; ++i)
                #pragma unroll
                for (int j = 0; j < 4; ++j)
                    #pragma unroll
                    for (int d = 0; d < 4; ++d) acc[i][j][d] = 0.f;
        }

        #pragma unroll
        for (int kh = 0; kh < 2; ++kh) {
            #pragma unroll
            for (int ks2 = 0; ks2 < 2; ++ks2) {
                const int ks = kh * 2 + ks2;
                uint32_t bfr[2][4];
                #pragma unroll
                for (int bl = 0; bl < 2; ++bl) {
                    uint32_t g = ks * 2 + a_ghi;
                    ldsm4(bfr[bl], b_addr0[bl] + slot * SM_B_BUF + ((g ^ b_gx[bl]) << 4));
                }
                uint32_t g = kc * 8 + ks * 2 + a_ghi;
                uint32_t off = ((g ^ a_rx) << 4);
                uint32_t afr[2][4];
                ldsm4(afr[0], a_addr0 + off);
                ldsm4(afr[1], a_addr0 + 8192 + off);
                #pragma unroll
                for (int mf = 0; mf < 2; ++mf)
                    #pragma unroll
                    for (int bl = 0; bl < 2; ++bl) {
                        mma16816(acc[mf][bl * 2],     afr[mf], bfr[bl][0], bfr[bl][2]);
                        mma16816(acc[mf][bl * 2 + 1], afr[mf], bfr[bl][1], bfr[bl][3]);
                    }
            }
        }

        if (kc == 3) {
            __half* ss = (__half*)(smem + SM_SS);
            int r0  = wm * 32 + (lane >> 2);
            int col0 = wn * 32 + ((lane & 3) << 1);
            #pragma unroll
            for (int nf = 0; nf < 4; ++nf) {
                int k0 = nt * 128 + col0 + nf * 8;
                float2 wq = *(const float2*)&g_wsq[k0];     // L1-resident
                #pragma unroll
                for (int mf = 0; mf < 2; ++mf) {
                    int r = r0 + mf * 16;
                    int col = col0 + nf * 8;
                    *(__half2*)&ss[r * SS_PITCH + col] =
                        __floats2half2_rn(wq.x - 2.f * acc[mf][nf][0],
                                          wq.y - 2.f * acc[mf][nf][1]);
                    *(__half2*)&ss[(r + 8) * SS_PITCH + col] =
                        __floats2half2_rn(wq.x - 2.f * acc[mf][nf][2],
                                          wq.y - 2.f * acc[mf][nf][3]);
                }
            }
            __syncthreads();
            {
                int r = tid >> 2, part = tid & 3;
                const uint4* src = (const uint4*)(smem + SM_SS + r * (SS_PITCH * 2) + part * 64);
                uint4* dst = (uint4*)(g_scores + (((size_t)(n0 + r)) << 10) + (nt << 7) + part * 32);
                #pragma unroll
                for (int j = 0; j < 4; ++j) dst[j] = src[j];
            }
        }
    }
}

// ---------------------------------------------------------------------------
// Streaming argmin + certify + (rare) exact rescore. One warp per row.
__global__ __launch_bounds__(512)
void argmin_kernel(const float* __restrict__ w) {
    const int tid  = threadIdx.x;
    const int lane = tid & 31;
    const int m = blockIdx.x * 16 + (tid >> 5);

    // xn from per-row partials
    float xsq = (lane < 8) ? __ldg(&g_xnp[lane * NN + m]) : 0.f;
    #pragma unroll
    for (int o = 4; o; o >>= 1) xsq += __shfl_xor_sync(0xffffffffu, xsq, o);
    xsq = __shfl_sync(0xffffffffu, xsq, 0);
    const float xn = sqrtf(xsq) * 1.0001f + 0.01f;
    const float E  = fmaf(xn, __uint_as_float(g_slmax_bits), E_CONST);

    // stream scores: 4 x uint4 per lane (coalesced 16B granules)
    const uint4* sp = (const uint4*)(g_scores + ((size_t)m << 10));
    uint4 v[4];
    #pragma unroll
    for (int i = 0; i < 4; ++i) v[i] = sp[i * 32 + lane];

    float s[32];
    #pragma unroll
    for (int i = 0; i < 4; ++i) {
        float2 f;
        f = __half22float2(*(__half2*)&v[i].x); s[i*8+0] = f.x; s[i*8+1] = f.y;
        f = __half22float2(*(((__half2*)&v[i].x) + 1)); s[i*8+2] = f.x; s[i*8+3] = f.y;
        f = __half22float2(*(__half2*)&v[i].z); s[i*8+4] = f.x; s[i*8+5] = f.y;
        f = __half22float2(*(((__half2*)&v[i].z) + 1)); s[i*8+6] = f.x; s[i*8+7] = f.y;
    }

    // per-lane min (index = (i*32+lane)*8 + j), then warp reduce
    float bestv = FLT_MAX; int besti = 0;
    #pragma unroll
    for (int i = 0; i < 4; ++i)
        #pragma unroll
        for (int j = 0; j < 8; ++j)
            if (s[i*8+j] < bestv) { bestv = s[i*8+j]; besti = (i * 32 + lane) * 8 + j; }
    #pragma unroll
    for (int o = 16; o; o >>= 1) {
        float ov = __shfl_xor_sync(0xffffffffu, bestv, o);
        int   oi = __shfl_xor_sync(0xffffffffu, besti, o);
        if (ov < bestv) { bestv = ov; besti = oi; }
    }

    // candidate mask (bit x = score i=x>>3, j=x&7)
    const float T = bestv + 2.f * E;
    uint32_t cm = 0;
    #pragma unroll
    for (int i = 0; i < 4; ++i)
        #pragma unroll
        for (int j = 0; j < 8; ++j)
            cm |= (s[i*8+j] <= T) ? (1u << (i*8+j)) : 0u;
    int cnt = __popc(cm);
    #pragma unroll
    for (int o = 16; o; o >>= 1) cnt += __shfl_xor_sync(0xffffffffu, cnt, o);

    if (cnt == 1) {
        if (lane == 0) g_ridx[m] = besti;    // certified exact argmin
        return;
    }

    // exact fp32 rescore of the candidate set (provably contains argmin)
    float zv[8];
    const float* zr = g_zt + ((size_t)m << 8);
    #pragma unroll
    for (int j = 0; j < 8; ++j) zv[j] = zr[j * 32 + lane];

    float best = FLT_MAX; int bi = 0x7fffffff;
    uint32_t act = __ballot_sync(0xffffffffu, cm != 0);
    while (act) {
        int src = __ffs(act) - 1; act &= act - 1;
        uint32_t mk = __shfl_sync(0xffffffffu, cm, src);
        while (mk) {
            int x = __ffs(mk) - 1; mk &= mk - 1;
            int k = ((x >> 3) * 32 + src) * 8 + (x & 7);
            float dot = 0.f;
            const float* wr = w + ((size_t)k << 8);
            #pragma unroll
            for (int j = 0; j < 8; ++j)
                dot = fmaf(zv[j], __ldg(&wr[j * 32 + lane]), dot);
            #pragma unroll
            for (int o = 16; o; o >>= 1) dot += __shfl_xor_sync(0xffffffffu, dot, o);
            float se = __ldg(&g_wsq[k]) - 2.f * dot;
            if (se < best || (se == best && k < bi)) { best = se; bi = k; }
        }
    }
    if (lane == 0) g_ridx[m] = bi;
}

// ---------------------------------------------------------------------------
__global__ __launch_bounds__(512)
void epilogue_kernel(const float* __restrict__ z, const float* __restrict__ w,
                     float* __restrict__ out) {
    extern __shared__ float qs[];       // [256 c][128 m]
    const int tid = threadIdx.x;
    const int n0  = blockIdx.x * BM;
    const int b   = n0 >> 10;
    const int hw0 = n0 & (HWD - 1);

    {
        int m = tid & 127, cpart = tid >> 7;
        const float4* wr = (const float4*)(w + ((size_t)g_ridx[n0 + m] << 8) + cpart * 64);
        #pragma unroll
        for (int g = 0; g < 16; ++g) {
            float4 v = wr[g];
            int cq = cpart * 64 + g * 4;
            qs[(cq + 0) * BM + m] = v.x;
            qs[(cq + 1) * BM + m] = v.y;
            qs[(cq + 2) * BM + m] = v.z;
            qs[(cq + 3) * BM + m] = v.w;
        }
    }
    __syncthreads();
    {
        float* out_bar = out + (size_t)NN * CC;
        const int cg = tid >> 5;
        const int r4 = (tid & 31) * 4;
        #pragma unroll 4
        for (int cc = 0; cc < 16; ++cc) {
            int cq = cg * 16 + cc;
            size_t zo = ((size_t)(b * CC + cq)) * HWD + hw0 + r4;
            float4 zvv = *(const float4*)(z + zo);
            float4 q   = *(const float4*)(qs + cq * BM + r4);
            float4 co;
            co.x = zvv.x + (q.x - zvv.x);
            co.y = zvv.y + (q.y - zvv.y);
            co.z = zvv.z + (q.z - zvv.z);
            co.w = zvv.w + (q.w - zvv.w);
            *(float4*)(out + zo)     = co;
            *(float4*)(out_bar + zo) = q;
        }
    }
}

// ---------------------------------------------------------------------------
extern "C" void kernel_launch(void* const* d_in, const int* in_sizes, int n_in,
                              void* d_out, int out_size) {
    const float* z = (const float*)d_in[0];
    const float* w = (const float*)d_in[1];
    if (n_in >= 2 && in_sizes[0] == KK * CC && in_sizes[1] == NN * CC) {
        const float* t = z; z = w; w = t;
    }
    float* out = (float*)d_out;

    static bool attr_set = false;
    if (!attr_set) {
        cudaFuncSetAttribute(vq_gemm_kernel, cudaFuncAttributeMaxDynamicSharedMemorySize,
                             SMEM_TOTAL);
        cudaFuncSetAttribute(epilogue_kernel, cudaFuncAttributeMaxDynamicSharedMemorySize,
                             EPI_SMEM);
        attr_set = true;
    }

    prep_w_kernel<<<KK / 8, 256>>>(w);
    zprep_kernel<<<dim3(CC / 32, HWD / 32, BB), dim3(32, 8)>>>(z);
    vq_gemm_kernel<<<NN / BM, 512, SMEM_TOTAL>>>();
    argmin_kernel<<<NN / 16, 512>>>(w);
    epilogue_kernel<<<NN / BM, 512, EPI_SMEM>>>(z, w, out);
}

// round 17
// speedup vs baseline: 1.0523x; 1.0523x over previous
#include <cuda_runtime.h>
#include <cuda_fp16.h>
#include <float.h>
#include <stdint.h>

// ---------------------------------------------------------------------------
#define BB   32
#define CC   256
#define HWD  1024
#define KK   1024
#define NN   (BB * HWD)        // 32768
#define BM   128               // query rows per CTA
#define NCHUNK 32              // 8 nt * 4 kc (single fp16 product)

// SMEM layout for GEMM kernel
#define SM_A        0                   // [128 m][256 k] fp16 swizzled = 65536
#define SM_B        65536               // 4 stages x [128 n][64 k] fp16 = 65536
#define SM_B_BUF    16384
#define SM_SS       131072              // score staging half[128][136] = 34816
#define SS_PITCH    136
#define SMEM_TOTAL  (131072 + 128 * SS_PITCH * 2)   // 165888
#define EPI_SMEM    (CC * BM * 4)                   // 131072

// Certified bound: |true - stored_score| <= xn*0.0035*sqrt(wsq) + 0.5
// (0.2 register-path slack validated in R10 + 0.3 fp16 score-storage rounding)
#define E_CONST 0.5f

// ---------------------------------------------------------------------------
// Device scratch (static globals — no allocation)
__device__ __align__(256) __half g_w1[KK * CC];              // w fp16 [n][k]
__device__ __align__(256) __half g_z1[NN * CC];              // z fp16 [m][k]
__device__ __align__(256) float  g_zt[NN * CC];              // z fp32 [m][c]
__device__ __align__(256) __half g_scores[(size_t)NN * KK];  // approx scores, fp16
__device__ float    g_wsq[KK];
__device__ unsigned g_slmax_bits;        // max over k of 0.0035*sqrt(wsq_k), float bits
__device__ float    g_xnp[8 * NN];       // per-row partial |x|^2 (8 c-blocks)
__device__ int      g_ridx[NN];

// ---------------------------------------------------------------------------
__device__ __forceinline__ uint32_t smem_u32(const void* p) {
    return (uint32_t)__cvta_generic_to_shared(p);
}
__device__ __forceinline__ void cpa16(uint32_t s, const void* g) {
    asm volatile("cp.async.cg.shared.global [%0], [%1], 16;\n" :: "r"(s), "l"(g));
}
#define CPA_COMMIT() asm volatile("cp.async.commit_group;\n" ::: "memory")
#define CPA_WAIT(n)  asm volatile("cp.async.wait_group %0;\n" :: "n"(n) : "memory")

__device__ __forceinline__ void ldsm4(uint32_t* r, uint32_t addr) {
    asm volatile("ldmatrix.sync.aligned.m8n8.x4.shared.b16 {%0,%1,%2,%3}, [%4];"
                 : "=r"(r[0]), "=r"(r[1]), "=r"(r[2]), "=r"(r[3]) : "r"(addr));
}
__device__ __forceinline__ void mma16816(float* d, const uint32_t* a,
                                         uint32_t b0, uint32_t b1) {
    asm volatile("mma.sync.aligned.m16n8k16.row.col.f32.f16.f16.f32 "
                 "{%0,%1,%2,%3}, {%4,%5,%6,%7}, {%8,%9}, {%0,%1,%2,%3};"
                 : "+f"(d[0]), "+f"(d[1]), "+f"(d[2]), "+f"(d[3])
                 : "r"(a[0]), "r"(a[1]), "r"(a[2]), "r"(a[3]), "r"(b0), "r"(b1));
}
__device__ __forceinline__ uint32_t hmin2u(uint32_t a, uint32_t b) {
    uint32_t d; asm("min.f16x2 %0, %1, %2;" : "=r"(d) : "r"(a), "r"(b)); return d;
}
__device__ __forceinline__ uint32_t hsetle2(uint32_t a, uint32_t b) {
    uint32_t d; asm("set.le.u32.f16x2 %0, %1, %2;" : "=r"(d) : "r"(a), "r"(b)); return d;
}

// ---------------------------------------------------------------------------
// Prep: w -> fp16 copy + wsq + global max slope. One warp per code.
__global__ void prep_w_kernel(const float* __restrict__ w) {
    int code = blockIdx.x * 8 + (threadIdx.x >> 5);
    int lane = threadIdx.x & 31;
    const float* row = w + (size_t)code * CC;
    float4 v0 = *(const float4*)(row + lane * 8);
    float4 v1 = *(const float4*)(row + lane * 8 + 4);
    float s = v0.x*v0.x + v0.y*v0.y + v0.z*v0.z + v0.w*v0.w
            + v1.x*v1.x + v1.y*v1.y + v1.z*v1.z + v1.w*v1.w;
    __half h[8];
    h[0]=__float2half_rn(v0.x); h[1]=__float2half_rn(v0.y);
    h[2]=__float2half_rn(v0.z); h[3]=__float2half_rn(v0.w);
    h[4]=__float2half_rn(v1.x); h[5]=__float2half_rn(v1.y);
    h[6]=__float2half_rn(v1.z); h[7]=__float2half_rn(v1.w);
    *(uint4*)(g_w1 + (size_t)code * CC + lane * 8) = *(uint4*)h;
    #pragma unroll
    for (int o = 16; o; o >>= 1) s += __shfl_down_sync(0xffffffffu, s, o);
    if (lane == 0) {
        g_wsq[code] = s;
        atomicMax(&g_slmax_bits, __float_as_uint(0.0035f * sqrtf(s)));
    }
}

// Transpose z -> g_z1 fp16 / g_zt fp32, plus per-row 32c-block norm partials.
__global__ void zprep_kernel(const float* __restrict__ z) {
    __shared__ float t[32][33];
    int c0  = blockIdx.x * 32;
    int hw0 = blockIdx.y * 32;
    int b   = blockIdx.z;
    int x = threadIdx.x, y0 = threadIdx.y;     // 32 x 8; warp = fixed y0
    const float* zb = z + ((size_t)b * CC) * HWD;
    #pragma unroll
    for (int yy = 0; yy < 32; yy += 8)
        t[y0 + yy][x] = zb[(size_t)(c0 + y0 + yy) * HWD + hw0 + x];
    __syncthreads();
    #pragma unroll
    for (int yy = 0; yy < 32; yy += 8) {
        int hwl = y0 + yy;
        float v = t[x][hwl];
        size_t o = (size_t)(b * HWD + hw0 + hwl) * CC + c0 + x;
        g_zt[o] = v;
        g_z1[o] = __float2half_rn(v);
        float p = v * v;
        #pragma unroll
        for (int sh = 16; sh; sh >>= 1) p += __shfl_xor_sync(0xffffffffu, p, sh);
        if (x == 0)
            g_xnp[(c0 >> 5) * NN + b * HWD + hw0 + hwl] = p;
    }
}

// ---------------------------------------------------------------------------
__device__ __forceinline__ void load_b_chunk(uint32_t Bbase, int c, int slot, int tid) {
    int nt = c >> 2, kc = c & 3;
    const __half* base = g_w1 + ((size_t)(nt * 128) << 8) + (kc << 6);
    uint32_t dst = Bbase + slot * SM_B_BUF;
    #pragma unroll
    for (int j = 0; j < 2; ++j) {
        int gi = j * 512 + tid;
        int r = gi >> 3, g = gi & 7;
        cpa16(dst + r * 128 + ((g ^ (r & 7)) << 4),
              base + ((size_t)r << 8) + (g << 3));
    }
}

// ---------------------------------------------------------------------------
// Bare 1-product HMMA GEMM; stores fp16 APPROX SCORES (wsq - 2*dot).
__global__ __launch_bounds__(512, 1)
void vq_gemm_kernel() {
    extern __shared__ __align__(1024) char smem[];
    const int tid  = threadIdx.x;
    const int lane = tid & 31;
    const int wid  = tid >> 5;
    const int wm   = wid >> 2;
    const int wn   = wid & 3;

    const int n0 = blockIdx.x * BM;

    const uint32_t sbase = smem_u32(smem);
    const uint32_t Abase = sbase + SM_A;
    const uint32_t Bbase = sbase + SM_B;

    #pragma unroll
    for (int j = 0; j < 8; ++j) {
        int gi = j * 512 + tid;
        int m = gi >> 5, g = gi & 31;
        cpa16(Abase + m * 512 + ((g ^ (m & 7)) << 4),
              g_z1 + ((size_t)(n0 + m) << 8) + (g << 3));
    }
    load_b_chunk(Bbase, 0, 0, tid);
    CPA_COMMIT();
    load_b_chunk(Bbase, 1, 1, tid);
    CPA_COMMIT();
    load_b_chunk(Bbase, 2, 2, tid);
    CPA_COMMIT();

    const uint32_t a_row = wm * 32 + (lane & 15);
    const uint32_t a_ghi = lane >> 4;
    const uint32_t a_rx  = a_row & 7;
    const uint32_t a_addr0 = Abase + a_row * 512;

    uint32_t b_addr0[2], b_gx[2];
    #pragma unroll
    for (int bl = 0; bl < 2; ++bl) {
        uint32_t nr = wn * 32 + bl * 16 + (lane & 15);
        b_addr0[bl] = Bbase + nr * 128;
        b_gx[bl] = nr & 7;
    }

    float acc[2][4][4];

    for (int c = 0; c < NCHUNK; ++c) {
        const int nt   = c >> 2;
        const int kc   = c & 3;
        const int slot = c & 3;

        if (c + 2 < NCHUNK)      CPA_WAIT(2);
        else if (c + 1 < NCHUNK) CPA_WAIT(1);
        else                     CPA_WAIT(0);
        __syncthreads();
        if (c + 3 < NCHUNK) {
            load_b_chunk(Bbase, c + 3, (c + 3) & 3, tid);
            CPA_COMMIT();
        }

        if (kc == 0) {
            #pragma unroll
            for (int i = 0; i < 2; ++i)
                #pragma unroll
                for (int j = 0; j < 4; ++j)
                    #pragma unroll
                    for (int d = 0; d < 4; ++d) acc[i][j][d] = 0.f;
        }

        #pragma unroll
        for (int kh = 0; kh < 2; ++kh) {
            #pragma unroll
            for (int ks2 = 0; ks2 < 2; ++ks2) {
                const int ks = kh * 2 + ks2;
                uint32_t bfr[2][4];
                #pragma unroll
                for (int bl = 0; bl < 2; ++bl) {
                    uint32_t g = ks * 2 + a_ghi;
                    ldsm4(bfr[bl], b_addr0[bl] + slot * SM_B_BUF + ((g ^ b_gx[bl]) << 4));
                }
                uint32_t g = kc * 8 + ks * 2 + a_ghi;
                uint32_t off = ((g ^ a_rx) << 4);
                uint32_t afr[2][4];
                ldsm4(afr[0], a_addr0 + off);
                ldsm4(afr[1], a_addr0 + 8192 + off);
                #pragma unroll
                for (int mf = 0; mf < 2; ++mf)
                    #pragma unroll
                    for (int bl = 0; bl < 2; ++bl) {
                        mma16816(acc[mf][bl * 2],     afr[mf], bfr[bl][0], bfr[bl][2]);
                        mma16816(acc[mf][bl * 2 + 1], afr[mf], bfr[bl][1], bfr[bl][3]);
                    }
            }
        }

        if (kc == 3) {
            __half* ss = (__half*)(smem + SM_SS);
            int r0  = wm * 32 + (lane >> 2);
            int col0 = wn * 32 + ((lane & 3) << 1);
            #pragma unroll
            for (int nf = 0; nf < 4; ++nf) {
                int k0 = nt * 128 + col0 + nf * 8;
                float2 wq = *(const float2*)&g_wsq[k0];     // L1-resident
                #pragma unroll
                for (int mf = 0; mf < 2; ++mf) {
                    int r = r0 + mf * 16;
                    int col = col0 + nf * 8;
                    *(__half2*)&ss[r * SS_PITCH + col] =
                        __floats2half2_rn(wq.x - 2.f * acc[mf][nf][0],
                                          wq.y - 2.f * acc[mf][nf][1]);
                    *(__half2*)&ss[(r + 8) * SS_PITCH + col] =
                        __floats2half2_rn(wq.x - 2.f * acc[mf][nf][2],
                                          wq.y - 2.f * acc[mf][nf][3]);
                }
            }
            __syncthreads();
            {
                int r = tid >> 2, part = tid & 3;
                const uint4* src = (const uint4*)(smem + SM_SS + r * (SS_PITCH * 2) + part * 64);
                uint4* dst = (uint4*)(g_scores + (((size_t)(n0 + r)) << 10) + (nt << 7) + part * 32);
                #pragma unroll
                for (int j = 0; j < 4; ++j) dst[j] = src[j];
            }
        }
    }
}

// ---------------------------------------------------------------------------
// fp16-domain streaming argmin + certify + (rare) exact rescore. Warp per row.
__global__ __launch_bounds__(512)
void argmin_kernel(const float* __restrict__ w) {
    const int tid  = threadIdx.x;
    const int lane = tid & 31;
    const int m = blockIdx.x * 16 + (tid >> 5);

    // xn from per-row partials
    float xsq = (lane < 8) ? __ldg(&g_xnp[lane * NN + m]) : 0.f;
    #pragma unroll
    for (int o = 4; o; o >>= 1) xsq += __shfl_xor_sync(0xffffffffu, xsq, o);
    xsq = __shfl_sync(0xffffffffu, xsq, 0);
    const float xn = sqrtf(xsq) * 1.0001f + 0.01f;
    const float E  = fmaf(xn, __uint_as_float(g_slmax_bits), E_CONST);

    // stream scores: 4 x uint4 per lane = 16 half2 packs
    const uint4* sp = (const uint4*)(g_scores + ((size_t)m << 10));
    uint32_t p[16];
    #pragma unroll
    for (int i = 0; i < 4; ++i) {
        uint4 v = sp[i * 32 + lane];
        p[i*4+0] = v.x; p[i*4+1] = v.y; p[i*4+2] = v.z; p[i*4+3] = v.w;
    }

    // packed fp16 min tree (no index tracking), then warp reduce
    uint32_t mn = p[0];
    #pragma unroll
    for (int i = 1; i < 16; ++i) mn = hmin2u(mn, p[i]);
    #pragma unroll
    for (int o = 16; o; o >>= 1) mn = hmin2u(mn, __shfl_xor_sync(0xffffffffu, mn, o));
    __half2 mh = *(__half2*)&mn;
    const float bestv = fminf(__low2float(mh), __high2float(mh));

    // threshold, rounded UP to fp16 (candidate superset preserved)
    const __half Th = __float2half_ru(bestv + 2.f * E);
    uint32_t T2;
    { __half2 t2 = __halves2half2(Th, Th); T2 = *(uint32_t*)&t2; }

    // candidate mask: bit x -> k = ((x>>3)*32 + lane)*8 + (x&7)
    uint32_t cm = 0;
    #pragma unroll
    for (int i = 0; i < 16; ++i) {
        uint32_t t = hsetle2(p[i], T2) & 0x10001u;
        cm |= ((t | (t >> 15)) & 3u) << (2 * i);
    }
    int cnt = __popc(cm);
    #pragma unroll
    for (int o = 16; o; o >>= 1) cnt += __shfl_xor_sync(0xffffffffu, cnt, o);

    if (cnt == 1) {
        // unique candidate == certified exact argmin; its bit encodes the index
        if (cm) {
            int x = __ffs(cm) - 1;
            g_ridx[m] = ((x >> 3) * 32 + lane) * 8 + (x & 7);
        }
        return;
    }

    // exact fp32 rescore of the candidate set (provably contains argmin)
    float zv[8];
    const float* zr = g_zt + ((size_t)m << 8);
    #pragma unroll
    for (int j = 0; j < 8; ++j) zv[j] = zr[j * 32 + lane];

    float best = FLT_MAX; int bi = 0x7fffffff;
    uint32_t act = __ballot_sync(0xffffffffu, cm != 0);
    while (act) {
        int src = __ffs(act) - 1; act &= act - 1;
        uint32_t mk = __shfl_sync(0xffffffffu, cm, src);
        while (mk) {
            int x = __ffs(mk) - 1; mk &= mk - 1;
            int k = ((x >> 3) * 32 + src) * 8 + (x & 7);
            float dot = 0.f;
            const float* wr = w + ((size_t)k << 8);
            #pragma unroll
            for (int j = 0; j < 8; ++j)
                dot = fmaf(zv[j], __ldg(&wr[j * 32 + lane]), dot);
            #pragma unroll
            for (int o = 16; o; o >>= 1) dot += __shfl_xor_sync(0xffffffffu, dot, o);
            float se = __ldg(&g_wsq[k]) - 2.f * dot;
            if (se < best || (se == best && k < bi)) { best = se; bi = k; }
        }
    }
    if (lane == 0) g_ridx[m] = bi;
}

// ---------------------------------------------------------------------------
__global__ __launch_bounds__(512)
void epilogue_kernel(const float* __restrict__ z, const float* __restrict__ w,
                     float* __restrict__ out) {
    extern __shared__ float qs[];       // [256 c][128 m]
    const int tid = threadIdx.x;
    const int n0  = blockIdx.x * BM;
    const int b   = n0 >> 10;
    const int hw0 = n0 & (HWD - 1);

    {
        int m = tid & 127, cpart = tid >> 7;
        const float4* wr = (const float4*)(w + ((size_t)g_ridx[n0 + m] << 8) + cpart * 64);
        #pragma unroll
        for (int g = 0; g < 16; ++g) {
            float4 v = wr[g];
            int cq = cpart * 64 + g * 4;
            qs[(cq + 0) * BM + m] = v.x;
            qs[(cq + 1) * BM + m] = v.y;
            qs[(cq + 2) * BM + m] = v.z;
            qs[(cq + 3) * BM + m] = v.w;
        }
    }
    __syncthreads();
    {
        float* out_bar = out + (size_t)NN * CC;
        const int cg = tid >> 5;
        const int r4 = (tid & 31) * 4;
        #pragma unroll 4
        for (int cc = 0; cc < 16; ++cc) {
            int cq = cg * 16 + cc;
            size_t zo = ((size_t)(b * CC + cq)) * HWD + hw0 + r4;
            float4 zvv = *(const float4*)(z + zo);
            float4 q   = *(const float4*)(qs + cq * BM + r4);
            float4 co;
            co.x = zvv.x + (q.x - zvv.x);
            co.y = zvv.y + (q.y - zvv.y);
            co.z = zvv.z + (q.z - zvv.z);
            co.w = zvv.w + (q.w - zvv.w);
            *(float4*)(out + zo)     = co;
            *(float4*)(out_bar + zo) = q;
        }
    }
}

// ---------------------------------------------------------------------------
extern "C" void kernel_launch(void* const* d_in, const int* in_sizes, int n_in,
                              void* d_out, int out_size) {
    const float* z = (const float*)d_in[0];
    const float* w = (const float*)d_in[1];
    if (n_in >= 2 && in_sizes[0] == KK * CC && in_sizes[1] == NN * CC) {
        const float* t = z; z = w; w = t;
    }
    float* out = (float*)d_out;

    static bool attr_set = false;
    if (!attr_set) {
        cudaFuncSetAttribute(vq_gemm_kernel, cudaFuncAttributeMaxDynamicSharedMemorySize,
                             SMEM_TOTAL);
        cudaFuncSetAttribute(epilogue_kernel, cudaFuncAttributeMaxDynamicSharedMemorySize,
                             EPI_SMEM);
        attr_set = true;
    }

    prep_w_kernel<<<KK / 8, 256>>>(w);
    zprep_kernel<<<dim3(CC / 32, HWD / 32, BB), dim3(32, 8)>>>(z);
    vq_gemm_kernel<<<NN / BM, 512, SMEM_TOTAL>>>();
    argmin_kernel<<<NN / 16, 512>>>(w);
    epilogue_kernel<<<NN / BM, 512, EPI_SMEM>>>(z, w, out);
}